// round 1
// baseline (speedup 1.0000x reference)
#include <cuda_runtime.h>

#define NMAX   50000
#define FDIM   128
#define HDIM   64
#define NGRAPH 256

// ------------------------- scratch (device globals; no allocation) ---------
static __device__ float g_agg1[NMAX * FDIM];
static __device__ float g_h1  [NMAX * HDIM];
static __device__ float g_agg2[NMAX * HDIM];
static __device__ float g_h2  [NMAX * HDIM];
static __device__ float g_agg3[NMAX * HDIM];
static __device__ float g_h3  [NMAX * HDIM];
static __device__ float g_stats[3 * 2 * HDIM];  // per layer: sum[64], sumsq[64]
static __device__ float g_bn   [3 * 2 * HDIM];  // per layer: scale[64], shift[64]

// ------------------------- init: zero scratch, out = fc_b ------------------
__global__ void k_init(float* __restrict__ out, const float* __restrict__ fc_b) {
    size_t tid    = (size_t)blockIdx.x * blockDim.x + threadIdx.x;
    size_t stride = (size_t)gridDim.x * blockDim.x;
    float4 z = make_float4(0.f, 0.f, 0.f, 0.f);
    float4* a1 = (float4*)g_agg1;
    for (size_t i = tid; i < (size_t)NMAX * FDIM / 4; i += stride) a1[i] = z;
    float4* a2 = (float4*)g_agg2;
    float4* a3 = (float4*)g_agg3;
    for (size_t i = tid; i < (size_t)NMAX * HDIM / 4; i += stride) { a2[i] = z; a3[i] = z; }
    if (tid < 3 * 2 * HDIM) g_stats[tid] = 0.f;
    if (tid < NGRAPH) out[tid] = fc_b[0];
}

// ------------------------- layer-1 scatter (F=128, warp per edge) ----------
__global__ void k_scatter128(const float* __restrict__ x, const int* __restrict__ ei,
                             float* __restrict__ agg, int E) {
    int t = blockIdx.x * blockDim.x + threadIdx.x;
    int e = t >> 5;
    if (e >= E) return;
    int lane = t & 31;
    int src = ei[e];
    int dst = ei[E + e];
    float4 v = *(const float4*)(x + (size_t)src * FDIM + lane * 4);
    atomicAdd((float4*)(agg + (size_t)dst * FDIM + lane * 4), v);
}

// ------------------- layer-2/3 scatter (F=64, fuses BN+ReLU of source) -----
__global__ void k_scatter64(const float* __restrict__ h, const float* __restrict__ sc,
                            const float* __restrict__ sh, const int* __restrict__ ei,
                            float* __restrict__ agg, int E) {
    int t = blockIdx.x * blockDim.x + threadIdx.x;
    int e = t >> 4;
    if (e >= E) return;
    int l = t & 15;
    int src = ei[e];
    int dst = ei[E + e];
    float4 v = *(const float4*)(h + (size_t)src * HDIM + l * 4);
    float4 a = ((const float4*)sc)[l];
    float4 b = ((const float4*)sh)[l];
    float4 r;
    r.x = fmaxf(fmaf(v.x, a.x, b.x), 0.f);
    r.y = fmaxf(fmaf(v.y, a.y, b.y), 0.f);
    r.z = fmaxf(fmaf(v.z, a.z, b.z), 0.f);
    r.w = fmaxf(fmaf(v.w, a.w, b.w), 0.f);
    atomicAdd((float4*)(agg + (size_t)dst * HDIM + l * 4), r);
}

// ------------------------- MLP layer 1 (in=128): h = relu(relu((x+agg)W1+b1)W2+b2)
__global__ void __launch_bounds__(128) k_mlp1(
    const float* __restrict__ x, const float* __restrict__ agg,
    const float* __restrict__ w1, const float* __restrict__ b1,
    const float* __restrict__ w2, const float* __restrict__ b2,
    float* __restrict__ hout, int N)
{
    __shared__ float sW1[FDIM * HDIM];  // 32 KB
    __shared__ float sW2[HDIM * HDIM];  // 16 KB  (total exactly 48 KB)
    for (int i = threadIdx.x; i < FDIM * HDIM; i += 128) sW1[i] = w1[i];
    for (int i = threadIdx.x; i < HDIM * HDIM; i += 128) sW2[i] = w2[i];
    __syncthreads();

    int node = blockIdx.x * 128 + threadIdx.x;
    if (node >= N) return;

    float acc[HDIM];
#pragma unroll
    for (int j = 0; j < HDIM; j++) acc[j] = __ldg(&b1[j]);

    const float4* xr = (const float4*)(x   + (size_t)node * FDIM);
    const float4* ar = (const float4*)(agg + (size_t)node * FDIM);
#pragma unroll 1
    for (int k4 = 0; k4 < FDIM / 4; k4++) {
        float4 xv = xr[k4], av = ar[k4];
        float v0 = xv.x + av.x, v1 = xv.y + av.y, v2 = xv.z + av.z, v3 = xv.w + av.w;
        const float* w = &sW1[k4 * 4 * HDIM];
#pragma unroll
        for (int j = 0; j < HDIM; j++)
            acc[j] = fmaf(v3, w[3 * HDIM + j],
                     fmaf(v2, w[2 * HDIM + j],
                     fmaf(v1, w[HDIM + j],
                     fmaf(v0, w[j], acc[j]))));
    }

    float acc2[HDIM];
#pragma unroll
    for (int j = 0; j < HDIM; j++) acc2[j] = __ldg(&b2[j]);
#pragma unroll 1
    for (int k = 0; k < HDIM; k += 4) {
        float v0 = fmaxf(acc[k + 0], 0.f);
        float v1 = fmaxf(acc[k + 1], 0.f);
        float v2 = fmaxf(acc[k + 2], 0.f);
        float v3 = fmaxf(acc[k + 3], 0.f);
        const float* w = &sW2[k * HDIM];
#pragma unroll
        for (int j = 0; j < HDIM; j++)
            acc2[j] = fmaf(v3, w[3 * HDIM + j],
                      fmaf(v2, w[2 * HDIM + j],
                      fmaf(v1, w[HDIM + j],
                      fmaf(v0, w[j], acc2[j]))));
    }

    float4* ho = (float4*)(hout + (size_t)node * HDIM);
#pragma unroll
    for (int j4 = 0; j4 < HDIM / 4; j4++) {
        float4 o;
        o.x = fmaxf(acc2[j4 * 4 + 0], 0.f);
        o.y = fmaxf(acc2[j4 * 4 + 1], 0.f);
        o.z = fmaxf(acc2[j4 * 4 + 2], 0.f);
        o.w = fmaxf(acc2[j4 * 4 + 3], 0.f);
        ho[j4] = o;
    }
}

// ---------- MLP layers 2/3 (in=64): v = relu(sc*hprev+sh) + agg, then 2-layer MLP
__global__ void __launch_bounds__(128) k_mlp64(
    const float* __restrict__ hprev, const float* __restrict__ agg,
    const float* __restrict__ bnsc, const float* __restrict__ bnsh,
    const float* __restrict__ w1, const float* __restrict__ b1,
    const float* __restrict__ w2, const float* __restrict__ b2,
    float* __restrict__ hout, int N)
{
    __shared__ float sW1[HDIM * HDIM];
    __shared__ float sW2[HDIM * HDIM];
    __shared__ float sSc[HDIM], sSh[HDIM];
    for (int i = threadIdx.x; i < HDIM * HDIM; i += 128) { sW1[i] = w1[i]; sW2[i] = w2[i]; }
    if (threadIdx.x < HDIM) { sSc[threadIdx.x] = bnsc[threadIdx.x]; sSh[threadIdx.x] = bnsh[threadIdx.x]; }
    __syncthreads();

    int node = blockIdx.x * 128 + threadIdx.x;
    if (node >= N) return;

    float acc[HDIM];
#pragma unroll
    for (int j = 0; j < HDIM; j++) acc[j] = __ldg(&b1[j]);

    const float4* hr = (const float4*)(hprev + (size_t)node * HDIM);
    const float4* ar = (const float4*)(agg   + (size_t)node * HDIM);
#pragma unroll 1
    for (int k4 = 0; k4 < HDIM / 4; k4++) {
        float4 hv = hr[k4], av = ar[k4];
        int k = k4 * 4;
        float v0 = fmaxf(fmaf(hv.x, sSc[k + 0], sSh[k + 0]), 0.f) + av.x;
        float v1 = fmaxf(fmaf(hv.y, sSc[k + 1], sSh[k + 1]), 0.f) + av.y;
        float v2 = fmaxf(fmaf(hv.z, sSc[k + 2], sSh[k + 2]), 0.f) + av.z;
        float v3 = fmaxf(fmaf(hv.w, sSc[k + 3], sSh[k + 3]), 0.f) + av.w;
        const float* w = &sW1[k * HDIM];
#pragma unroll
        for (int j = 0; j < HDIM; j++)
            acc[j] = fmaf(v3, w[3 * HDIM + j],
                     fmaf(v2, w[2 * HDIM + j],
                     fmaf(v1, w[HDIM + j],
                     fmaf(v0, w[j], acc[j]))));
    }

    float acc2[HDIM];
#pragma unroll
    for (int j = 0; j < HDIM; j++) acc2[j] = __ldg(&b2[j]);
#pragma unroll 1
    for (int k = 0; k < HDIM; k += 4) {
        float v0 = fmaxf(acc[k + 0], 0.f);
        float v1 = fmaxf(acc[k + 1], 0.f);
        float v2 = fmaxf(acc[k + 2], 0.f);
        float v3 = fmaxf(acc[k + 3], 0.f);
        const float* w = &sW2[k * HDIM];
#pragma unroll
        for (int j = 0; j < HDIM; j++)
            acc2[j] = fmaf(v3, w[3 * HDIM + j],
                      fmaf(v2, w[2 * HDIM + j],
                      fmaf(v1, w[HDIM + j],
                      fmaf(v0, w[j], acc2[j]))));
    }

    float4* ho = (float4*)(hout + (size_t)node * HDIM);
#pragma unroll
    for (int j4 = 0; j4 < HDIM / 4; j4++) {
        float4 o;
        o.x = fmaxf(acc2[j4 * 4 + 0], 0.f);
        o.y = fmaxf(acc2[j4 * 4 + 1], 0.f);
        o.z = fmaxf(acc2[j4 * 4 + 2], 0.f);
        o.w = fmaxf(acc2[j4 * 4 + 3], 0.f);
        ho[j4] = o;
    }
}

// ------------------------- BN stats: per-feature sum / sumsq ---------------
__global__ void k_stats(const float* __restrict__ h, float* __restrict__ sum,
                        float* __restrict__ sumsq, int N) {
    int f = threadIdx.x & (HDIM - 1);
    int g = threadIdx.x >> 6;  // 0..3: 4 nodes in flight per block
    float s = 0.f, sq = 0.f;
    for (int i = blockIdx.x * 4 + g; i < N; i += gridDim.x * 4) {
        float v = h[(size_t)i * HDIM + f];
        s += v;
        sq = fmaf(v, v, sq);
    }
    __shared__ float ss[256], ssq[256];
    ss[threadIdx.x] = s; ssq[threadIdx.x] = sq;
    __syncthreads();
    if (threadIdx.x < HDIM) {
        s  = ss [threadIdx.x] + ss [64 + threadIdx.x] + ss [128 + threadIdx.x] + ss [192 + threadIdx.x];
        sq = ssq[threadIdx.x] + ssq[64 + threadIdx.x] + ssq[128 + threadIdx.x] + ssq[192 + threadIdx.x];
        atomicAdd(&sum[threadIdx.x], s);
        atomicAdd(&sumsq[threadIdx.x], sq);
    }
}

// ------------------------- BN finalize: scale/shift ------------------------
__global__ void k_bnfinal(const float* __restrict__ sum, const float* __restrict__ sumsq,
                          const float* __restrict__ gamma, const float* __restrict__ beta,
                          float* __restrict__ sc, float* __restrict__ sh, float invN) {
    int f = threadIdx.x;
    float mu  = sum[f] * invN;
    float var = fmaxf(sumsq[f] * invN - mu * mu, 0.f);
    float rs  = rsqrtf(var + 1e-5f);
    float s   = gamma[f] * rs;
    sc[f] = s;
    sh[f] = fmaf(-mu, s, beta[f]);
}

// -------------- final: relu(BN(h3)) dot fc_w, pooled into out[batch] -------
__global__ void k_final(const float* __restrict__ h, const float* __restrict__ sc,
                        const float* __restrict__ sh, const int* __restrict__ batch,
                        const float* __restrict__ fcw, float* __restrict__ out, int N) {
    int node = blockIdx.x * blockDim.x + threadIdx.x;
    if (node >= N) return;
    float s = 0.f;
    const float4* hr = (const float4*)(h + (size_t)node * HDIM);
#pragma unroll
    for (int k4 = 0; k4 < HDIM / 4; k4++) {
        float4 hv = hr[k4];
        float4 a  = ((const float4*)sc)[k4];
        float4 b  = ((const float4*)sh)[k4];
        float4 w  = ((const float4*)fcw)[k4];
        s = fmaf(fmaxf(fmaf(hv.x, a.x, b.x), 0.f), w.x, s);
        s = fmaf(fmaxf(fmaf(hv.y, a.y, b.y), 0.f), w.y, s);
        s = fmaf(fmaxf(fmaf(hv.z, a.z, b.z), 0.f), w.z, s);
        s = fmaf(fmaxf(fmaf(hv.w, a.w, b.w), 0.f), w.w, s);
    }
    atomicAdd(&out[batch[node]], s);
}

// ---------------------------------------------------------------------------
extern "C" void kernel_launch(void* const* d_in, const int* in_sizes, int n_in,
                              void* d_out, int out_size) {
    const float* x     = (const float*)d_in[0];
    const int*   ei    = (const int*)  d_in[1];
    const int*   batch = (const int*)  d_in[2];
    const float* c1_w1 = (const float*)d_in[3];
    const float* c1_b1 = (const float*)d_in[4];
    const float* c1_w2 = (const float*)d_in[5];
    const float* c1_b2 = (const float*)d_in[6];
    const float* c1_g  = (const float*)d_in[7];
    const float* c1_be = (const float*)d_in[8];
    const float* c2_w1 = (const float*)d_in[9];
    const float* c2_b1 = (const float*)d_in[10];
    const float* c2_w2 = (const float*)d_in[11];
    const float* c2_b2 = (const float*)d_in[12];
    const float* c2_g  = (const float*)d_in[13];
    const float* c2_be = (const float*)d_in[14];
    const float* c3_w1 = (const float*)d_in[15];
    const float* c3_b1 = (const float*)d_in[16];
    const float* c3_w2 = (const float*)d_in[17];
    const float* c3_b2 = (const float*)d_in[18];
    const float* c3_g  = (const float*)d_in[19];
    const float* c3_be = (const float*)d_in[20];
    const float* fc_w  = (const float*)d_in[21];
    const float* fc_b  = (const float*)d_in[22];
    float* out = (float*)d_out;

    int N = in_sizes[0] / FDIM;
    int E = in_sizes[1] / 2;
    float invN = 1.0f / (float)N;

    float *agg1, *h1, *agg2, *h2, *agg3, *h3, *stats, *bn;
    cudaGetSymbolAddress((void**)&agg1,  g_agg1);
    cudaGetSymbolAddress((void**)&h1,    g_h1);
    cudaGetSymbolAddress((void**)&agg2,  g_agg2);
    cudaGetSymbolAddress((void**)&h2,    g_h2);
    cudaGetSymbolAddress((void**)&agg3,  g_agg3);
    cudaGetSymbolAddress((void**)&h3,    g_h3);
    cudaGetSymbolAddress((void**)&stats, g_stats);
    cudaGetSymbolAddress((void**)&bn,    g_bn);

    k_init<<<2048, 256>>>(out, fc_b);

    // -------- layer 1 --------
    k_scatter128<<<(E * 32 + 255) / 256, 256>>>(x, ei, agg1, E);
    k_mlp1<<<(N + 127) / 128, 128>>>(x, agg1, c1_w1, c1_b1, c1_w2, c1_b2, h1, N);
    k_stats<<<256, 256>>>(h1, stats + 0, stats + HDIM, N);
    k_bnfinal<<<1, HDIM>>>(stats + 0, stats + HDIM, c1_g, c1_be, bn + 0, bn + HDIM, invN);

    // -------- layer 2 --------
    k_scatter64<<<(E * 16 + 255) / 256, 256>>>(h1, bn + 0, bn + HDIM, ei, agg2, E);
    k_mlp64<<<(N + 127) / 128, 128>>>(h1, agg2, bn + 0, bn + HDIM,
                                      c2_w1, c2_b1, c2_w2, c2_b2, h2, N);
    k_stats<<<256, 256>>>(h2, stats + 2 * HDIM, stats + 3 * HDIM, N);
    k_bnfinal<<<1, HDIM>>>(stats + 2 * HDIM, stats + 3 * HDIM, c2_g, c2_be,
                           bn + 2 * HDIM, bn + 3 * HDIM, invN);

    // -------- layer 3 --------
    k_scatter64<<<(E * 16 + 255) / 256, 256>>>(h2, bn + 2 * HDIM, bn + 3 * HDIM, ei, agg3, E);
    k_mlp64<<<(N + 127) / 128, 128>>>(h2, agg3, bn + 2 * HDIM, bn + 3 * HDIM,
                                      c3_w1, c3_b1, c3_w2, c3_b2, h3, N);
    k_stats<<<256, 256>>>(h3, stats + 4 * HDIM, stats + 5 * HDIM, N);
    k_bnfinal<<<1, HDIM>>>(stats + 4 * HDIM, stats + 5 * HDIM, c3_g, c3_be,
                           bn + 4 * HDIM, bn + 5 * HDIM, invN);

    // -------- pool + head --------
    k_final<<<(N + 255) / 256, 256>>>(h3, bn + 4 * HDIM, bn + 5 * HDIM, batch, fc_w, out, N);
}

// round 2
// speedup vs baseline: 1.2064x; 1.2064x over previous
#include <cuda_runtime.h>

#define NMAX   50000
#define FDIM   128
#define HDIM   64
#define NGRAPH 256

// ------------------------- scratch (device globals; no allocation) ---------
static __device__ float g_y   [NMAX * HDIM];   // x @ c1_w1
static __device__ float g_agg1[NMAX * HDIM];
static __device__ float g_h1  [NMAX * HDIM];
static __device__ float g_agg2[NMAX * HDIM];
static __device__ float g_h2  [NMAX * HDIM];
static __device__ float g_agg3[NMAX * HDIM];
static __device__ float g_h3  [NMAX * HDIM];
static __device__ float g_stats[3 * 2 * HDIM];  // per layer: sum[64], sumsq[64]
static __device__ float g_bn   [3 * 2 * HDIM];  // per layer: scale[64], shift[64]

// ------------------------- init: zero scratch, out = fc_b ------------------
__global__ void k_init(float* __restrict__ out, const float* __restrict__ fc_b) {
    size_t tid    = (size_t)blockIdx.x * blockDim.x + threadIdx.x;
    size_t stride = (size_t)gridDim.x * blockDim.x;
    float4 z = make_float4(0.f, 0.f, 0.f, 0.f);
    float4* a1 = (float4*)g_agg1;
    float4* a2 = (float4*)g_agg2;
    float4* a3 = (float4*)g_agg3;
    for (size_t i = tid; i < (size_t)NMAX * HDIM / 4; i += stride) {
        a1[i] = z; a2[i] = z; a3[i] = z;
    }
    if (tid < 3 * 2 * HDIM) g_stats[tid] = 0.f;
    if (tid < NGRAPH) out[tid] = fc_b[0];
}

// ------------------------- pre-transform: y = x @ W1 (no bias) -------------
__global__ void __launch_bounds__(128) k_xform(
    const float* __restrict__ x, const float* __restrict__ w1,
    float* __restrict__ y, int N)
{
    __shared__ float sW1[FDIM * HDIM];  // 32 KB
    for (int i = threadIdx.x; i < FDIM * HDIM; i += 128) sW1[i] = w1[i];
    __syncthreads();

    int node = blockIdx.x * 128 + threadIdx.x;
    if (node >= N) return;

    float acc[HDIM];
#pragma unroll
    for (int j = 0; j < HDIM; j++) acc[j] = 0.f;

    const float4* xr = (const float4*)(x + (size_t)node * FDIM);
#pragma unroll 1
    for (int k4 = 0; k4 < FDIM / 4; k4++) {
        float4 xv = xr[k4];
        const float* w = &sW1[k4 * 4 * HDIM];
#pragma unroll
        for (int j = 0; j < HDIM; j++)
            acc[j] = fmaf(xv.w, w[3 * HDIM + j],
                     fmaf(xv.z, w[2 * HDIM + j],
                     fmaf(xv.y, w[HDIM + j],
                     fmaf(xv.x, w[j], acc[j]))));
    }

    float4* yo = (float4*)(y + (size_t)node * HDIM);
#pragma unroll
    for (int j4 = 0; j4 < HDIM / 4; j4++)
        yo[j4] = make_float4(acc[j4 * 4 + 0], acc[j4 * 4 + 1],
                             acc[j4 * 4 + 2], acc[j4 * 4 + 3]);
}

// --------------- layer-1 scatter on y (64-dim, plain add) ------------------
__global__ void k_scatter64p(const float* __restrict__ y, const int* __restrict__ ei,
                             float* __restrict__ agg, int E) {
    int t = blockIdx.x * blockDim.x + threadIdx.x;
    int e = t >> 4;
    if (e >= E) return;
    int l = t & 15;
    int src = ei[e];
    int dst = ei[E + e];
    float4 v = *(const float4*)(y + (size_t)src * HDIM + l * 4);
    atomicAdd((float4*)(agg + (size_t)dst * HDIM + l * 4), v);
}

// ------------------- layer-2/3 scatter (fuses BN+ReLU of source) -----------
__global__ void k_scatter64(const float* __restrict__ h, const float* __restrict__ sc,
                            const float* __restrict__ sh, const int* __restrict__ ei,
                            float* __restrict__ agg, int E) {
    int t = blockIdx.x * blockDim.x + threadIdx.x;
    int e = t >> 4;
    if (e >= E) return;
    int l = t & 15;
    int src = ei[e];
    int dst = ei[E + e];
    float4 v = *(const float4*)(h + (size_t)src * HDIM + l * 4);
    float4 a = ((const float4*)sc)[l];
    float4 b = ((const float4*)sh)[l];
    float4 r;
    r.x = fmaxf(fmaf(v.x, a.x, b.x), 0.f);
    r.y = fmaxf(fmaf(v.y, a.y, b.y), 0.f);
    r.z = fmaxf(fmaf(v.z, a.z, b.z), 0.f);
    r.w = fmaxf(fmaf(v.w, a.w, b.w), 0.f);
    atomicAdd((float4*)(agg + (size_t)dst * HDIM + l * 4), r);
}

// -------- MLP layer 1 (post-xform): h = relu(relu(y+agg+b1) @ W2 + b2) -----
__global__ void __launch_bounds__(128) k_mlpA(
    const float* __restrict__ y, const float* __restrict__ agg,
    const float* __restrict__ b1,
    const float* __restrict__ w2, const float* __restrict__ b2,
    float* __restrict__ hout, int N)
{
    __shared__ float sW2[HDIM * HDIM];
    __shared__ float sB1[HDIM];
    for (int i = threadIdx.x; i < HDIM * HDIM; i += 128) sW2[i] = w2[i];
    if (threadIdx.x < HDIM) sB1[threadIdx.x] = b1[threadIdx.x];
    __syncthreads();

    int node = blockIdx.x * 128 + threadIdx.x;
    if (node >= N) return;

    float acc2[HDIM];
#pragma unroll
    for (int j = 0; j < HDIM; j++) acc2[j] = __ldg(&b2[j]);

    const float4* yr = (const float4*)(y   + (size_t)node * HDIM);
    const float4* ar = (const float4*)(agg + (size_t)node * HDIM);
#pragma unroll 1
    for (int k4 = 0; k4 < HDIM / 4; k4++) {
        float4 yv = yr[k4], av = ar[k4];
        int k = k4 * 4;
        float v0 = fmaxf(yv.x + av.x + sB1[k + 0], 0.f);
        float v1 = fmaxf(yv.y + av.y + sB1[k + 1], 0.f);
        float v2 = fmaxf(yv.z + av.z + sB1[k + 2], 0.f);
        float v3 = fmaxf(yv.w + av.w + sB1[k + 3], 0.f);
        const float* w = &sW2[k * HDIM];
#pragma unroll
        for (int j = 0; j < HDIM; j++)
            acc2[j] = fmaf(v3, w[3 * HDIM + j],
                      fmaf(v2, w[2 * HDIM + j],
                      fmaf(v1, w[HDIM + j],
                      fmaf(v0, w[j], acc2[j]))));
    }

    float4* ho = (float4*)(hout + (size_t)node * HDIM);
#pragma unroll
    for (int j4 = 0; j4 < HDIM / 4; j4++) {
        float4 o;
        o.x = fmaxf(acc2[j4 * 4 + 0], 0.f);
        o.y = fmaxf(acc2[j4 * 4 + 1], 0.f);
        o.z = fmaxf(acc2[j4 * 4 + 2], 0.f);
        o.w = fmaxf(acc2[j4 * 4 + 3], 0.f);
        ho[j4] = o;
    }
}

// ---------- MLP layers 2/3 (in=64): v = relu(sc*hprev+sh) + agg, 2-layer MLP
__global__ void __launch_bounds__(128) k_mlp64(
    const float* __restrict__ hprev, const float* __restrict__ agg,
    const float* __restrict__ bnsc, const float* __restrict__ bnsh,
    const float* __restrict__ w1, const float* __restrict__ b1,
    const float* __restrict__ w2, const float* __restrict__ b2,
    float* __restrict__ hout, int N)
{
    __shared__ float sW1[HDIM * HDIM];
    __shared__ float sW2[HDIM * HDIM];
    __shared__ float sSc[HDIM], sSh[HDIM];
    for (int i = threadIdx.x; i < HDIM * HDIM; i += 128) { sW1[i] = w1[i]; sW2[i] = w2[i]; }
    if (threadIdx.x < HDIM) { sSc[threadIdx.x] = bnsc[threadIdx.x]; sSh[threadIdx.x] = bnsh[threadIdx.x]; }
    __syncthreads();

    int node = blockIdx.x * 128 + threadIdx.x;
    if (node >= N) return;

    float acc[HDIM];
#pragma unroll
    for (int j = 0; j < HDIM; j++) acc[j] = __ldg(&b1[j]);

    const float4* hr = (const float4*)(hprev + (size_t)node * HDIM);
    const float4* ar = (const float4*)(agg   + (size_t)node * HDIM);
#pragma unroll 1
    for (int k4 = 0; k4 < HDIM / 4; k4++) {
        float4 hv = hr[k4], av = ar[k4];
        int k = k4 * 4;
        float v0 = fmaxf(fmaf(hv.x, sSc[k + 0], sSh[k + 0]), 0.f) + av.x;
        float v1 = fmaxf(fmaf(hv.y, sSc[k + 1], sSh[k + 1]), 0.f) + av.y;
        float v2 = fmaxf(fmaf(hv.z, sSc[k + 2], sSh[k + 2]), 0.f) + av.z;
        float v3 = fmaxf(fmaf(hv.w, sSc[k + 3], sSh[k + 3]), 0.f) + av.w;
        const float* w = &sW1[k * HDIM];
#pragma unroll
        for (int j = 0; j < HDIM; j++)
            acc[j] = fmaf(v3, w[3 * HDIM + j],
                     fmaf(v2, w[2 * HDIM + j],
                     fmaf(v1, w[HDIM + j],
                     fmaf(v0, w[j], acc[j]))));
    }

    float acc2[HDIM];
#pragma unroll
    for (int j = 0; j < HDIM; j++) acc2[j] = __ldg(&b2[j]);
#pragma unroll 1
    for (int k = 0; k < HDIM; k += 4) {
        float v0 = fmaxf(acc[k + 0], 0.f);
        float v1 = fmaxf(acc[k + 1], 0.f);
        float v2 = fmaxf(acc[k + 2], 0.f);
        float v3 = fmaxf(acc[k + 3], 0.f);
        const float* w = &sW2[k * HDIM];
#pragma unroll
        for (int j = 0; j < HDIM; j++)
            acc2[j] = fmaf(v3, w[3 * HDIM + j],
                      fmaf(v2, w[2 * HDIM + j],
                      fmaf(v1, w[HDIM + j],
                      fmaf(v0, w[j], acc2[j]))));
    }

    float4* ho = (float4*)(hout + (size_t)node * HDIM);
#pragma unroll
    for (int j4 = 0; j4 < HDIM / 4; j4++) {
        float4 o;
        o.x = fmaxf(acc2[j4 * 4 + 0], 0.f);
        o.y = fmaxf(acc2[j4 * 4 + 1], 0.f);
        o.z = fmaxf(acc2[j4 * 4 + 2], 0.f);
        o.w = fmaxf(acc2[j4 * 4 + 3], 0.f);
        ho[j4] = o;
    }
}

// ----------- BN stats: per-feature sum / sumsq (float4, coalesced) ---------
__global__ void __launch_bounds__(256) k_stats(
    const float* __restrict__ h, float* __restrict__ sum,
    float* __restrict__ sumsq, int N)
{
    int f4      = threadIdx.x & 15;   // which float4 of the 16 per row
    int rowLane = threadIdx.x >> 4;   // 0..15 rows per block tile
    float4 s = make_float4(0.f, 0.f, 0.f, 0.f);
    float4 q = make_float4(0.f, 0.f, 0.f, 0.f);
    const float4* hv = (const float4*)h;
    for (int row = blockIdx.x * 16 + rowLane; row < N; row += gridDim.x * 16) {
        float4 v = hv[(size_t)row * 16 + f4];
        s.x += v.x; s.y += v.y; s.z += v.z; s.w += v.w;
        q.x = fmaf(v.x, v.x, q.x); q.y = fmaf(v.y, v.y, q.y);
        q.z = fmaf(v.z, v.z, q.z); q.w = fmaf(v.w, v.w, q.w);
    }
    __shared__ float4 ss[256], sq[256];
    ss[threadIdx.x] = s; sq[threadIdx.x] = q;
    __syncthreads();
#pragma unroll
    for (int off = 128; off >= 16; off >>= 1) {
        if (threadIdx.x < off) {
            float4 a = ss[threadIdx.x], b = ss[threadIdx.x + off];
            ss[threadIdx.x] = make_float4(a.x + b.x, a.y + b.y, a.z + b.z, a.w + b.w);
            float4 c = sq[threadIdx.x], d = sq[threadIdx.x + off];
            sq[threadIdx.x] = make_float4(c.x + d.x, c.y + d.y, c.z + d.z, c.w + d.w);
        }
        __syncthreads();
    }
    if (threadIdx.x < 16) {
        float4 S = ss[threadIdx.x], Q = sq[threadIdx.x];
        atomicAdd(&sum[threadIdx.x * 4 + 0], S.x);
        atomicAdd(&sum[threadIdx.x * 4 + 1], S.y);
        atomicAdd(&sum[threadIdx.x * 4 + 2], S.z);
        atomicAdd(&sum[threadIdx.x * 4 + 3], S.w);
        atomicAdd(&sumsq[threadIdx.x * 4 + 0], Q.x);
        atomicAdd(&sumsq[threadIdx.x * 4 + 1], Q.y);
        atomicAdd(&sumsq[threadIdx.x * 4 + 2], Q.z);
        atomicAdd(&sumsq[threadIdx.x * 4 + 3], Q.w);
    }
}

// ------------------------- BN finalize: scale/shift ------------------------
__global__ void k_bnfinal(const float* __restrict__ sum, const float* __restrict__ sumsq,
                          const float* __restrict__ gamma, const float* __restrict__ beta,
                          float* __restrict__ sc, float* __restrict__ sh, float invN) {
    int f = threadIdx.x;
    float mu  = sum[f] * invN;
    float var = fmaxf(sumsq[f] * invN - mu * mu, 0.f);
    float rs  = rsqrtf(var + 1e-5f);
    float s   = gamma[f] * rs;
    sc[f] = s;
    sh[f] = fmaf(-mu, s, beta[f]);
}

// -------------- final: relu(BN(h3)) dot fc_w, pooled into out[batch] -------
__global__ void k_final(const float* __restrict__ h, const float* __restrict__ sc,
                        const float* __restrict__ sh, const int* __restrict__ batch,
                        const float* __restrict__ fcw, float* __restrict__ out, int N) {
    int node = blockIdx.x * blockDim.x + threadIdx.x;
    if (node >= N) return;
    float s = 0.f;
    const float4* hr = (const float4*)(h + (size_t)node * HDIM);
#pragma unroll
    for (int k4 = 0; k4 < HDIM / 4; k4++) {
        float4 hv = hr[k4];
        float4 a  = ((const float4*)sc)[k4];
        float4 b  = ((const float4*)sh)[k4];
        float4 w  = ((const float4*)fcw)[k4];
        s = fmaf(fmaxf(fmaf(hv.x, a.x, b.x), 0.f), w.x, s);
        s = fmaf(fmaxf(fmaf(hv.y, a.y, b.y), 0.f), w.y, s);
        s = fmaf(fmaxf(fmaf(hv.z, a.z, b.z), 0.f), w.z, s);
        s = fmaf(fmaxf(fmaf(hv.w, a.w, b.w), 0.f), w.w, s);
    }
    atomicAdd(&out[batch[node]], s);
}

// ---------------------------------------------------------------------------
extern "C" void kernel_launch(void* const* d_in, const int* in_sizes, int n_in,
                              void* d_out, int out_size) {
    const float* x     = (const float*)d_in[0];
    const int*   ei    = (const int*)  d_in[1];
    const int*   batch = (const int*)  d_in[2];
    const float* c1_w1 = (const float*)d_in[3];
    const float* c1_b1 = (const float*)d_in[4];
    const float* c1_w2 = (const float*)d_in[5];
    const float* c1_b2 = (const float*)d_in[6];
    const float* c1_g  = (const float*)d_in[7];
    const float* c1_be = (const float*)d_in[8];
    const float* c2_w1 = (const float*)d_in[9];
    const float* c2_b1 = (const float*)d_in[10];
    const float* c2_w2 = (const float*)d_in[11];
    const float* c2_b2 = (const float*)d_in[12];
    const float* c2_g  = (const float*)d_in[13];
    const float* c2_be = (const float*)d_in[14];
    const float* c3_w1 = (const float*)d_in[15];
    const float* c3_b1 = (const float*)d_in[16];
    const float* c3_w2 = (const float*)d_in[17];
    const float* c3_b2 = (const float*)d_in[18];
    const float* c3_g  = (const float*)d_in[19];
    const float* c3_be = (const float*)d_in[20];
    const float* fc_w  = (const float*)d_in[21];
    const float* fc_b  = (const float*)d_in[22];
    float* out = (float*)d_out;

    int N = in_sizes[0] / FDIM;
    int E = in_sizes[1] / 2;
    float invN = 1.0f / (float)N;

    float *y, *agg1, *h1, *agg2, *h2, *agg3, *h3, *stats, *bn;
    cudaGetSymbolAddress((void**)&y,     g_y);
    cudaGetSymbolAddress((void**)&agg1,  g_agg1);
    cudaGetSymbolAddress((void**)&h1,    g_h1);
    cudaGetSymbolAddress((void**)&agg2,  g_agg2);
    cudaGetSymbolAddress((void**)&h2,    g_h2);
    cudaGetSymbolAddress((void**)&agg3,  g_agg3);
    cudaGetSymbolAddress((void**)&h3,    g_h3);
    cudaGetSymbolAddress((void**)&stats, g_stats);
    cudaGetSymbolAddress((void**)&bn,    g_bn);

    k_init<<<2048, 256>>>(out, fc_b);

    // -------- layer 1 (pre-transformed) --------
    k_xform<<<(N + 127) / 128, 128>>>(x, c1_w1, y, N);
    k_scatter64p<<<(E * 16 + 255) / 256, 256>>>(y, ei, agg1, E);
    k_mlpA<<<(N + 127) / 128, 128>>>(y, agg1, c1_b1, c1_w2, c1_b2, h1, N);
    k_stats<<<512, 256>>>(h1, stats + 0, stats + HDIM, N);
    k_bnfinal<<<1, HDIM>>>(stats + 0, stats + HDIM, c1_g, c1_be, bn + 0, bn + HDIM, invN);

    // -------- layer 2 --------
    k_scatter64<<<(E * 16 + 255) / 256, 256>>>(h1, bn + 0, bn + HDIM, ei, agg2, E);
    k_mlp64<<<(N + 127) / 128, 128>>>(h1, agg2, bn + 0, bn + HDIM,
                                      c2_w1, c2_b1, c2_w2, c2_b2, h2, N);
    k_stats<<<512, 256>>>(h2, stats + 2 * HDIM, stats + 3 * HDIM, N);
    k_bnfinal<<<1, HDIM>>>(stats + 2 * HDIM, stats + 3 * HDIM, c2_g, c2_be,
                           bn + 2 * HDIM, bn + 3 * HDIM, invN);

    // -------- layer 3 --------
    k_scatter64<<<(E * 16 + 255) / 256, 256>>>(h2, bn + 2 * HDIM, bn + 3 * HDIM, ei, agg3, E);
    k_mlp64<<<(N + 127) / 128, 128>>>(h2, agg3, bn + 2 * HDIM, bn + 3 * HDIM,
                                      c3_w1, c3_b1, c3_w2, c3_b2, h3, N);
    k_stats<<<512, 256>>>(h3, stats + 4 * HDIM, stats + 5 * HDIM, N);
    k_bnfinal<<<1, HDIM>>>(stats + 4 * HDIM, stats + 5 * HDIM, c3_g, c3_be,
                           bn + 4 * HDIM, bn + 5 * HDIM, invN);

    // -------- pool + head --------
    k_final<<<(N + 255) / 256, 256>>>(h3, bn + 4 * HDIM, bn + 5 * HDIM, batch, fc_w, out, N);
}